// round 3
// baseline (speedup 1.0000x reference)
#include <cuda_runtime.h>

// out[i,j,l,e] = A[mi][e] + ds * B[mi][e]
//   mi = (j < traj_len[i]) ? 1 : 0
//   ds = mi ? mat2[(traj_loc[i,j]-1)*L_MAX + l] : 0
//
// Optimization: output (134 MB) ~= L2 (126 MB). Output is rewritten every
// graph replay and never read in between. Split the output address range:
//   - first RESIDENT_BLOCKS*32KB: default (write-back, evict-normal) stores
//     -> lines stay dirty-resident in L2 across replays -> ~zero DRAM traffic
//   - rest: evict-first streaming stores -> bounded DRAM stream
// This converts a DRAM-write-bound kernel into an L2-write-bound one.

#define N_    32
#define M_    128
#define LMAX_ 128
#define EMB_  64
#define RESIDENT_BLOCKS 3072   // 3072 * 32KB = 96 MB kept L2-resident

__global__ __launch_bounds__(256, 8)
void embed_kernel(const int* __restrict__ traj_loc,
                  const float* __restrict__ mat2,
                  const int* __restrict__ traj_len,
                  const float* __restrict__ sl,
                  const float* __restrict__ su,
                  const float* __restrict__ tl,
                  const float* __restrict__ tu,
                  float* __restrict__ out)
{
    const float inv_su = 1.0f / 10000.0f;   // 1/SU
    const float inv_tu = 1.0f / 86400.0f;   // 1/TU

    int ij = blockIdx.x;            // 0 .. N*M-1
    int i  = ij >> 7;               // / M_
    int j  = ij & (M_ - 1);

    bool mask = (j < __ldg(traj_len + i));
    int  mi   = mask ? 1 : 0;
    int  loc  = __ldg(traj_loc + ij) - 1;   // 0-indexed row of mat2

    // thread mapping: 16 float4 lanes over EMB=64, 16 l-rows, 8 l-iterations
    int e4 = threadIdx.x & 15;      // float4 index within EMB
    int l0 = threadIdx.x >> 4;      // 0..15

    int wbase = mi * EMB_ + e4 * 4;
    float4 s_l = *reinterpret_cast<const float4*>(sl + wbase);
    float4 s_u = *reinterpret_cast<const float4*>(su + wbase);
    float4 t_l = *reinterpret_cast<const float4*>(tl + wbase);
    float4 t_u = *reinterpret_cast<const float4*>(tu + wbase);

    float4 A, B;
    A.x = s_l.x + t_l.x;  A.y = s_l.y + t_l.y;
    A.z = s_l.z + t_l.z;  A.w = s_l.w + t_l.w;
    B.x = (s_u.x - s_l.x) * inv_su + (t_u.x - t_l.x) * inv_tu;
    B.y = (s_u.y - s_l.y) * inv_su + (t_u.y - t_l.y) * inv_tu;
    B.z = (s_u.z - s_l.z) * inv_su + (t_u.z - t_l.z) * inv_tu;
    B.w = (s_u.w - s_l.w) * inv_su + (t_u.w - t_l.w) * inv_tu;

    const float* m2row = mat2 + (long)loc * LMAX_;
    float4* out4 = reinterpret_cast<float4*>(out) + (long)ij * (LMAX_ * EMB_ / 4);

    // Batch the 8 broadcast loads first (max MLP), then the 8 stores.
    float ds[8];
    #pragma unroll
    for (int k = 0; k < 8; k++) {
        int l = l0 + k * 16;
        ds[k] = mask ? __ldg(m2row + l) : 0.0f;
    }

    float4 r[8];
    #pragma unroll
    for (int k = 0; k < 8; k++) {
        r[k].x = fmaf(ds[k], B.x, A.x);
        r[k].y = fmaf(ds[k], B.y, A.y);
        r[k].z = fmaf(ds[k], B.z, A.z);
        r[k].w = fmaf(ds[k], B.w, A.w);
    }

    if (ij < RESIDENT_BLOCKS) {
        // L2-resident slab: default write-back stores; lines re-dirtied each
        // replay, never written to DRAM.
        #pragma unroll
        for (int k = 0; k < 8; k++) {
            int l = l0 + k * 16;
            out4[l * (EMB_ / 4) + e4] = r[k];
        }
    } else {
        // Streaming slab: evict-first, goes to DRAM every replay.
        #pragma unroll
        for (int k = 0; k < 8; k++) {
            int l = l0 + k * 16;
            __stcs(&out4[l * (EMB_ / 4) + e4], r[k]);
        }
    }
}

extern "C" void kernel_launch(void* const* d_in, const int* in_sizes, int n_in,
                              void* d_out, int out_size)
{
    // Expected order: traj_loc[4096] i32, mat2[524288] f32, vec[4096] f32,
    // traj_len[32] i32, (l_max[1] i32 — maybe), emb_sl[128], emb_su[128],
    // emb_tl[128], emb_tu[128] f32.
    const int*   traj_loc = (const int*)  d_in[0];
    const float* mat2     = (const float*)d_in[1];
    const int*   traj_len = (const int*)  d_in[3];

    // Locate embedding block: skip scalar l_max if present.
    int eb = 4;
    if (n_in >= 9 && in_sizes[4] == 1) eb = 5;
    const float* sl = (const float*)d_in[eb + 0];
    const float* su = (const float*)d_in[eb + 1];
    const float* tl = (const float*)d_in[eb + 2];
    const float* tu = (const float*)d_in[eb + 3];

    embed_kernel<<<N_ * M_, 256>>>(traj_loc, mat2, traj_len,
                                   sl, su, tl, tu, (float*)d_out);
}

// round 4
// speedup vs baseline: 1.4552x; 1.4552x over previous
#include <cuda_runtime.h>

// out[i,j,l,e] = A[mi][e] + ds * B[mi][e]
//   mi = (j < traj_len[i]) ? 1 : 0
//   ds = mi ? mat2[(traj_loc[i,j]-1)*L_MAX + l] : 0
//   A[m][e] = sl[m*EMB+e] + tl[m*EMB+e]
//   B[m][e] = (su[m*EMB+e]-sl[m*EMB+e])*(1/SU) + (tu[m*EMB+e]-tl[m*EMB+e])*(1/TU)
//
// DRAM-write-bound: 134 MB f32 output @ ~5.45 TB/s sustained write BW.
// All stores are evict-first streaming (.cs) — R3 proved partial L2
// residency regresses (demand dirty-evictions on the store path).

#define N_    32
#define M_    128
#define LMAX_ 128
#define EMB_  64

__global__ __launch_bounds__(256, 8)
void embed_kernel(const int* __restrict__ traj_loc,
                  const float* __restrict__ mat2,
                  const int* __restrict__ traj_len,
                  const float* __restrict__ sl,
                  const float* __restrict__ su,
                  const float* __restrict__ tl,
                  const float* __restrict__ tu,
                  float* __restrict__ out)
{
    const float inv_su = 1.0f / 10000.0f;   // 1/SU
    const float inv_tu = 1.0f / 86400.0f;   // 1/TU

    int ij = blockIdx.x;            // 0 .. N*M-1
    int i  = ij >> 7;               // / M_
    int j  = ij & (M_ - 1);

    bool mask = (j < __ldg(traj_len + i));
    int  mi   = mask ? 1 : 0;
    int  loc  = __ldg(traj_loc + ij) - 1;   // 0-indexed row of mat2

    // thread mapping: 16 float4 lanes over EMB=64, 16 l-rows, 8 l-iterations
    int e4 = threadIdx.x & 15;      // float4 index within EMB
    int l0 = threadIdx.x >> 4;      // 0..15

    int wbase = mi * EMB_ + e4 * 4;
    float4 s_l = *reinterpret_cast<const float4*>(sl + wbase);
    float4 s_u = *reinterpret_cast<const float4*>(su + wbase);
    float4 t_l = *reinterpret_cast<const float4*>(tl + wbase);
    float4 t_u = *reinterpret_cast<const float4*>(tu + wbase);

    float4 A, B;
    A.x = s_l.x + t_l.x;  A.y = s_l.y + t_l.y;
    A.z = s_l.z + t_l.z;  A.w = s_l.w + t_l.w;
    B.x = (s_u.x - s_l.x) * inv_su + (t_u.x - t_l.x) * inv_tu;
    B.y = (s_u.y - s_l.y) * inv_su + (t_u.y - t_l.y) * inv_tu;
    B.z = (s_u.z - s_l.z) * inv_su + (t_u.z - t_l.z) * inv_tu;
    B.w = (s_u.w - s_l.w) * inv_su + (t_u.w - t_l.w) * inv_tu;

    const float* m2row = mat2 + (long)loc * LMAX_;
    float4* out4 = reinterpret_cast<float4*>(out) + (long)ij * (LMAX_ * EMB_ / 4);

    // Batch the 8 broadcast loads first (max MLP), then the 8 streaming stores.
    float ds[8];
    #pragma unroll
    for (int k = 0; k < 8; k++) {
        int l = l0 + k * 16;
        ds[k] = mask ? __ldg(m2row + l) : 0.0f;
    }

    #pragma unroll
    for (int k = 0; k < 8; k++) {
        int l = l0 + k * 16;
        float4 r;
        r.x = fmaf(ds[k], B.x, A.x);
        r.y = fmaf(ds[k], B.y, A.y);
        r.z = fmaf(ds[k], B.z, A.z);
        r.w = fmaf(ds[k], B.w, A.w);
        // evict-first streaming store: output never re-read; keep L2 draining
        __stcs(&out4[l * (EMB_ / 4) + e4], r);
    }
}

extern "C" void kernel_launch(void* const* d_in, const int* in_sizes, int n_in,
                              void* d_out, int out_size)
{
    // Expected order: traj_loc[4096] i32, mat2[524288] f32, vec[4096] f32,
    // traj_len[32] i32, (l_max[1] i32 — maybe), emb_sl[128], emb_su[128],
    // emb_tl[128], emb_tu[128] f32.
    const int*   traj_loc = (const int*)  d_in[0];
    const float* mat2     = (const float*)d_in[1];
    const int*   traj_len = (const int*)  d_in[3];

    // Locate embedding block: skip scalar l_max if present.
    int eb = 4;
    if (n_in >= 9 && in_sizes[4] == 1) eb = 5;
    const float* sl = (const float*)d_in[eb + 0];
    const float* su = (const float*)d_in[eb + 1];
    const float* tl = (const float*)d_in[eb + 2];
    const float* tu = (const float*)d_in[eb + 3];

    embed_kernel<<<N_ * M_, 256>>>(traj_loc, mat2, traj_len,
                                   sl, su, tl, tu, (float*)d_out);
}